// round 2
// baseline (speedup 1.0000x reference)
#include <cuda_runtime.h>
#include <cuda_bf16.h>
#include <cstdint>

#define N_NODES 100000
#define N_EDGES 1600000
#define IN_CH   128
#define HEADS   4
#define OUT_CH  32
#define HC      128   // HEADS*OUT_CH
#define NEG_SLOPE 0.2f
#define EPS_F 1e-16f

// ---------------- scratch (device globals; no allocation allowed) ----------
__device__ float    g_xl[(size_t)N_NODES * HC];
__device__ float    g_xr[(size_t)N_NODES * HC];
__device__ float    g_e [(size_t)N_EDGES * HEADS];   // logits, then exp(logit-max)
__device__ unsigned g_m [(size_t)N_NODES * HEADS];   // order-encoded float max
__device__ float    g_den[(size_t)N_NODES * HEADS];  // softmax denominator

// monotone order-preserving float<->uint encoding (for atomicMax on floats)
__device__ __forceinline__ unsigned enc_f(float f) {
    unsigned u = __float_as_uint(f);
    return (u & 0x80000000u) ? ~u : (u | 0x80000000u);
}
__device__ __forceinline__ float dec_f(unsigned u) {
    return __uint_as_float((u & 0x80000000u) ? (u ^ 0x80000000u) : ~u);
}
__device__ __forceinline__ float lrelu(float v) {
    return fmaxf(v, 0.f) + NEG_SLOPE * fminf(v, 0.f);
}

// ---------------- K0: init out=bias, m=-inf(enc 0), den=0 ------------------
__global__ void k_init(float* __restrict__ out, const float* __restrict__ bias) {
    int i = blockIdx.x * 256 + threadIdx.x;
    if (i < N_NODES * HC) out[i] = bias[i & (HC - 1)];
    if (i < N_NODES * HEADS) { g_m[i] = 0u; g_den[i] = 0.f; }
}

// ---------------- K1: y = x @ W (64x128 tile, BK=32) -----------------------
// grid.x = ceil(N/64), grid.y selects (W_l -> g_xl) or (W_r -> g_xr)
__global__ __launch_bounds__(128) void k_gemm(
    const float* __restrict__ X,
    const float* __restrict__ Wl,
    const float* __restrict__ Wr)
{
    const float* W = blockIdx.y ? Wr : Wl;
    float* Y = blockIdx.y ? g_xr : g_xl;

    __shared__ float xs[32][68];    // transposed x chunk [k][row], padded
    __shared__ float ws[32][128];   // W chunk [k][col]

    const int tid  = threadIdx.x;           // 0..127
    const int rr   = tid & 7;                // 8 row groups of 8
    const int cr   = tid >> 3;               // 16 col groups of 8
    const int row0 = blockIdx.x * 64;

    float acc[8][8];
#pragma unroll
    for (int i = 0; i < 8; i++)
#pragma unroll
        for (int j = 0; j < 8; j++) acc[i][j] = 0.f;

    for (int ch = 0; ch < 4; ch++) {
        const int k0 = ch * 32;
        // load x tile: 64 rows x 32 cols, transposed into xs
#pragma unroll
        for (int i = 0; i < 4; i++) {
            int li = tid + i * 128;          // 0..511
            int r  = li >> 3;                // 8 float4 per row
            int kq = (li & 7) * 4;
            float4 v = make_float4(0.f, 0.f, 0.f, 0.f);
            if (row0 + r < N_NODES)
                v = *(const float4*)&X[(size_t)(row0 + r) * IN_CH + k0 + kq];
            xs[kq + 0][r] = v.x; xs[kq + 1][r] = v.y;
            xs[kq + 2][r] = v.z; xs[kq + 3][r] = v.w;
        }
        // load W chunk: 32 x 128
#pragma unroll
        for (int i = 0; i < 8; i++) {
            int li = tid + i * 128;          // 0..1023
            int k  = li >> 5;                // 32 float4 per row
            int c  = (li & 31) * 4;
            *(float4*)&ws[k][c] = *(const float4*)&W[(size_t)(k0 + k) * HC + c];
        }
        __syncthreads();
#pragma unroll
        for (int kk = 0; kk < 32; kk++) {
            float xv[8], wv[8];
            *(float4*)&xv[0] = *(float4*)&xs[kk][rr * 8];
            *(float4*)&xv[4] = *(float4*)&xs[kk][rr * 8 + 4];
            *(float4*)&wv[0] = *(float4*)&ws[kk][cr * 8];
            *(float4*)&wv[4] = *(float4*)&ws[kk][cr * 8 + 4];
#pragma unroll
            for (int i = 0; i < 8; i++)
#pragma unroll
                for (int j = 0; j < 8; j++)
                    acc[i][j] = fmaf(xv[i], wv[j], acc[i][j]);
        }
        __syncthreads();
    }
#pragma unroll
    for (int i = 0; i < 8; i++) {
        int r = row0 + rr * 8 + i;
        if (r < N_NODES) {
            *(float4*)&Y[(size_t)r * HC + cr * 8] =
                make_float4(acc[i][0], acc[i][1], acc[i][2], acc[i][3]);
            *(float4*)&Y[(size_t)r * HC + cr * 8 + 4] =
                make_float4(acc[i][4], acc[i][5], acc[i][6], acc[i][7]);
        }
    }
}

// ---------------- K2: per-edge logits + segment max ------------------------
// one warp per edge; lane handles 4 channels (one head per 8-lane group)
__global__ __launch_bounds__(256) void k_logits(
    const float* __restrict__ att,
    const int* __restrict__ ei)
{
    int e = blockIdx.x * 8 + (threadIdx.x >> 5);
    if (e >= N_EDGES) return;
    int lane = threadIdx.x & 31;

    int src = ei[e];
    int dst = ei[N_EDGES + e];

    float4 a = *(const float4*)&g_xl[(size_t)src * HC + lane * 4];
    float4 b = *(const float4*)&g_xr[(size_t)dst * HC + lane * 4];
    float4 t = *(const float4*)&att[lane * 4];

    float p = lrelu(a.x + b.x) * t.x;
    p = fmaf(lrelu(a.y + b.y), t.y, p);
    p = fmaf(lrelu(a.z + b.z), t.z, p);
    p = fmaf(lrelu(a.w + b.w), t.w, p);

    p += __shfl_xor_sync(0xffffffffu, p, 1);
    p += __shfl_xor_sync(0xffffffffu, p, 2);
    p += __shfl_xor_sync(0xffffffffu, p, 4);

    if ((lane & 7) == 0) {
        int h = lane >> 3;
        g_e[(size_t)e * HEADS + h] = p;
        atomicMax(&g_m[(size_t)dst * HEADS + h], enc_f(p));
    }
}

// ---------------- K3: exp(e - m[dst]) and segment sum ----------------------
__global__ __launch_bounds__(256) void k_expsum(const int* __restrict__ ei) {
    int idx = blockIdx.x * 256 + threadIdx.x;
    if (idx >= N_EDGES * HEADS) return;
    int e = idx >> 2, h = idx & 3;
    int dst = ei[N_EDGES + e];
    float v = expf(g_e[idx] - dec_f(g_m[(size_t)dst * HEADS + h]));
    g_e[idx] = v;
    atomicAdd(&g_den[(size_t)dst * HEADS + h], v);
}

// ---------------- K4: alpha-weighted scatter-add ----------------------------
__global__ __launch_bounds__(256) void k_scatter(
    float* __restrict__ out,
    const int* __restrict__ ei)
{
    int e = blockIdx.x * 8 + (threadIdx.x >> 5);
    if (e >= N_EDGES) return;
    int lane = threadIdx.x & 31;

    int src = ei[e];
    int dst = ei[N_EDGES + e];
    int h = lane >> 3;

    float alpha = g_e[(size_t)e * HEADS + h] /
                  (g_den[(size_t)dst * HEADS + h] + EPS_F);

    float4 v = *(const float4*)&g_xl[(size_t)src * HC + lane * 4];
    v.x *= alpha; v.y *= alpha; v.z *= alpha; v.w *= alpha;

    float* p = &out[(size_t)dst * HC + lane * 4];
    asm volatile("red.global.add.v4.f32 [%0], {%1,%2,%3,%4};"
                 :: "l"(p), "f"(v.x), "f"(v.y), "f"(v.z), "f"(v.w)
                 : "memory");
}

// ---------------- launch ----------------------------------------------------
extern "C" void kernel_launch(void* const* d_in, const int* in_sizes, int n_in,
                              void* d_out, int out_size)
{
    const float* x    = (const float*)d_in[0];
    const int*   ei   = (const int*)d_in[1];
    const float* Wl   = (const float*)d_in[2];
    const float* Wr   = (const float*)d_in[3];
    const float* att  = (const float*)d_in[4];
    const float* bias = (const float*)d_in[5];
    float* out = (float*)d_out;

    k_init<<<(N_NODES * HC + 255) / 256, 256>>>(out, bias);

    dim3 ggrid((N_NODES + 63) / 64, 2);
    k_gemm<<<ggrid, 128>>>(x, Wl, Wr);

    k_logits<<<(N_EDGES + 7) / 8, 256>>>(att, ei);
    k_expsum<<<(N_EDGES * HEADS + 255) / 256, 256>>>(ei);
    k_scatter<<<(N_EDGES + 7) / 8, 256>>>(out, ei);
}

// round 3
// speedup vs baseline: 1.1065x; 1.1065x over previous
#include <cuda_runtime.h>
#include <cuda_bf16.h>
#include <cstdint>

#define N_NODES 100000
#define N_EDGES 1600000
#define IN_CH   128
#define HEADS   4
#define OUT_CH  32
#define HC      128   // HEADS*OUT_CH
#define NEG_SLOPE 0.2f
#define EPS_F 1e-16f

// ---------------- scratch (device globals; no allocation allowed) ----------
__device__ float    g_xl[(size_t)N_NODES * HC];
__device__ float    g_xr[(size_t)N_NODES * HC];
__device__ float    g_e [(size_t)N_EDGES * HEADS];   // logits, then exp(logit-max)
__device__ unsigned g_m [(size_t)N_NODES * HEADS];   // order-encoded float max
__device__ float    g_den[(size_t)N_NODES * HEADS];  // softmax denominator

// monotone order-preserving float<->uint encoding (for atomicMax on floats)
__device__ __forceinline__ unsigned enc_f(float f) {
    unsigned u = __float_as_uint(f);
    return (u & 0x80000000u) ? ~u : (u | 0x80000000u);
}
__device__ __forceinline__ float dec_f(unsigned u) {
    return __uint_as_float((u & 0x80000000u) ? (u ^ 0x80000000u) : ~u);
}
__device__ __forceinline__ float lrelu(float v) {
    return fmaxf(v, 0.f) + NEG_SLOPE * fminf(v, 0.f);
}
__device__ __forceinline__ uint32_t to_tf32(float f) {
    uint32_t o;
    asm("cvt.rna.tf32.f32 %0, %1;" : "=r"(o) : "f"(f));
    return o;
}

// ---------------- K0: init out=bias, m=-inf(enc 0), den=0 ------------------
__global__ void k_init(float* __restrict__ out, const float* __restrict__ bias) {
    int i = blockIdx.x * 256 + threadIdx.x;
    if (i < N_NODES * HC) out[i] = bias[i & (HC - 1)];
    if (i < N_NODES * HEADS) { g_m[i] = 0u; g_den[i] = 0.f; }
}

// ---------------- K1: fused dual GEMM via tf32 tensor-core mma --------------
// One block = 64 node rows x 256 output cols (128 for W_l -> g_xl, 128 for
// W_r -> g_xr). X tile staged once per K-chunk and shared by both halves.
// 8 warps: warp w -> row tile r = w&3 (16 rows), half c = w>>2.
__global__ __launch_bounds__(256) void k_gemm(
    const float* __restrict__ X,
    const float* __restrict__ Wl,
    const float* __restrict__ Wr)
{
    __shared__ uint32_t xs[64][36];    // X chunk [m][k] tf32, pad 36 (conflict-free A frags)
    __shared__ uint32_t ws[32][264];   // W chunk [k][n] tf32, n<128: W_l, n>=128: W_r; pad 264

    const int tid  = threadIdx.x;
    const int warp = tid >> 5;
    const int lane = tid & 31;
    const int r     = warp & 3;     // row tile (16 rows)
    const int cHalf = warp >> 2;    // 0 -> W_l/g_xl, 1 -> W_r/g_xr
    const int row0 = blockIdx.x * 64;

    const int qr = lane >> 2;       // quad row 0..7
    const int ql = lane & 3;        // quad lane 0..3

    float c[16][4];
#pragma unroll
    for (int j = 0; j < 16; j++)
#pragma unroll
        for (int q = 0; q < 4; q++) c[j][q] = 0.f;

    for (int chunk = 0; chunk < 4; chunk++) {
        const int k0 = chunk * 32;
        if (chunk) __syncthreads();
        // stage X chunk: 64 x 32 floats (512 float4, 2 per thread), tf32-convert
#pragma unroll
        for (int i = 0; i < 2; i++) {
            int li = tid + i * 256;
            int m  = li >> 3;
            int kq = (li & 7) * 4;
            float4 v = make_float4(0.f, 0.f, 0.f, 0.f);
            if (row0 + m < N_NODES)
                v = *(const float4*)&X[(size_t)(row0 + m) * IN_CH + k0 + kq];
            xs[m][kq + 0] = to_tf32(v.x); xs[m][kq + 1] = to_tf32(v.y);
            xs[m][kq + 2] = to_tf32(v.z); xs[m][kq + 3] = to_tf32(v.w);
        }
        // stage W chunk: 32 x 256 floats (2048 float4, 8 per thread)
#pragma unroll
        for (int i = 0; i < 8; i++) {
            int li = tid + i * 256;
            int k  = li >> 6;
            int cq = (li & 63) * 4;
            const float* Wsrc = (cq < 128) ? Wl : Wr;
            int cc = (cq < 128) ? cq : (cq - 128);
            float4 v = *(const float4*)&Wsrc[(size_t)(k0 + k) * HC + cc];
            ws[k][cq + 0] = to_tf32(v.x); ws[k][cq + 1] = to_tf32(v.y);
            ws[k][cq + 2] = to_tf32(v.z); ws[k][cq + 3] = to_tf32(v.w);
        }
        __syncthreads();

#pragma unroll
        for (int ks = 0; ks < 4; ks++) {
            const int kk = ks * 8;
            uint32_t a0 = xs[r * 16 + qr    ][kk + ql    ];
            uint32_t a1 = xs[r * 16 + qr + 8][kk + ql    ];
            uint32_t a2 = xs[r * 16 + qr    ][kk + ql + 4];
            uint32_t a3 = xs[r * 16 + qr + 8][kk + ql + 4];
#pragma unroll
            for (int j = 0; j < 16; j++) {
                int nb = cHalf * 128 + j * 8 + qr;
                uint32_t b0 = ws[kk + ql    ][nb];
                uint32_t b1 = ws[kk + ql + 4][nb];
                asm volatile(
                    "mma.sync.aligned.m16n8k8.row.col.f32.tf32.tf32.f32 "
                    "{%0,%1,%2,%3}, {%4,%5,%6,%7}, {%8,%9}, {%0,%1,%2,%3};"
                    : "+f"(c[j][0]), "+f"(c[j][1]), "+f"(c[j][2]), "+f"(c[j][3])
                    : "r"(a0), "r"(a1), "r"(a2), "r"(a3), "r"(b0), "r"(b1));
            }
        }
    }

    float* Y = cHalf ? g_xr : g_xl;
    const int rbase = row0 + r * 16 + qr;
#pragma unroll
    for (int j = 0; j < 16; j++) {
        int col = j * 8 + 2 * ql;
        if (rbase < N_NODES)
            *(float2*)&Y[(size_t)rbase * HC + col] = make_float2(c[j][0], c[j][1]);
        if (rbase + 8 < N_NODES)
            *(float2*)&Y[(size_t)(rbase + 8) * HC + col] = make_float2(c[j][2], c[j][3]);
    }
}

// ---------------- K2: per-edge logits + segment max ------------------------
// one warp per edge; lane handles 4 channels (one head per 8-lane group)
__global__ __launch_bounds__(256) void k_logits(
    const float* __restrict__ att,
    const int* __restrict__ ei)
{
    int e = blockIdx.x * 8 + (threadIdx.x >> 5);
    if (e >= N_EDGES) return;
    int lane = threadIdx.x & 31;

    int src = ei[e];
    int dst = ei[N_EDGES + e];

    float4 a = *(const float4*)&g_xl[(size_t)src * HC + lane * 4];
    float4 b = *(const float4*)&g_xr[(size_t)dst * HC + lane * 4];
    float4 t = *(const float4*)&att[lane * 4];

    float p = lrelu(a.x + b.x) * t.x;
    p = fmaf(lrelu(a.y + b.y), t.y, p);
    p = fmaf(lrelu(a.z + b.z), t.z, p);
    p = fmaf(lrelu(a.w + b.w), t.w, p);

    p += __shfl_xor_sync(0xffffffffu, p, 1);
    p += __shfl_xor_sync(0xffffffffu, p, 2);
    p += __shfl_xor_sync(0xffffffffu, p, 4);

    if ((lane & 7) == 0) {
        int h = lane >> 3;
        g_e[(size_t)e * HEADS + h] = p;
        atomicMax(&g_m[(size_t)dst * HEADS + h], enc_f(p));
    }
}

// ---------------- K3: exp(e - m[dst]) and segment sum ----------------------
__global__ __launch_bounds__(256) void k_expsum(const int* __restrict__ ei) {
    int idx = blockIdx.x * 256 + threadIdx.x;
    if (idx >= N_EDGES * HEADS) return;
    int e = idx >> 2, h = idx & 3;
    int dst = ei[N_EDGES + e];
    float v = __expf(g_e[idx] - dec_f(g_m[(size_t)dst * HEADS + h]));
    g_e[idx] = v;
    atomicAdd(&g_den[(size_t)dst * HEADS + h], v);
}

// ---------------- K4: alpha-weighted scatter-add ----------------------------
__global__ __launch_bounds__(256) void k_scatter(
    float* __restrict__ out,
    const int* __restrict__ ei)
{
    int e = blockIdx.x * 8 + (threadIdx.x >> 5);
    if (e >= N_EDGES) return;
    int lane = threadIdx.x & 31;

    int src = ei[e];
    int dst = ei[N_EDGES + e];
    int h = lane >> 3;

    float alpha = g_e[(size_t)e * HEADS + h] /
                  (g_den[(size_t)dst * HEADS + h] + EPS_F);

    float4 v = *(const float4*)&g_xl[(size_t)src * HC + lane * 4];
    v.x *= alpha; v.y *= alpha; v.z *= alpha; v.w *= alpha;

    float* p = &out[(size_t)dst * HC + lane * 4];
    asm volatile("red.global.add.v4.f32 [%0], {%1,%2,%3,%4};"
                 :: "l"(p), "f"(v.x), "f"(v.y), "f"(v.z), "f"(v.w)
                 : "memory");
}

// ---------------- launch ----------------------------------------------------
extern "C" void kernel_launch(void* const* d_in, const int* in_sizes, int n_in,
                              void* d_out, int out_size)
{
    const float* x    = (const float*)d_in[0];
    const int*   ei   = (const int*)d_in[1];
    const float* Wl   = (const float*)d_in[2];
    const float* Wr   = (const float*)d_in[3];
    const float* att  = (const float*)d_in[4];
    const float* bias = (const float*)d_in[5];
    float* out = (float*)d_out;

    k_init<<<(N_NODES * HC + 255) / 256, 256>>>(out, bias);

    k_gemm<<<(N_NODES + 63) / 64, 256>>>(x, Wl, Wr);

    k_logits<<<(N_EDGES + 7) / 8, 256>>>(att, ei);
    k_expsum<<<(N_EDGES * HEADS + 255) / 256, 256>>>(ei);
    k_scatter<<<(N_EDGES + 7) / 8, 256>>>(out, ei);
}

// round 4
// speedup vs baseline: 2.6715x; 2.4143x over previous
#include <cuda_runtime.h>
#include <cuda_bf16.h>
#include <cstdint>

#define N_NODES 100000
#define N_EDGES 1600000
#define IN_CH   128
#define HEADS   4
#define OUT_CH  32
#define HC      128
#define NEG_SLOPE 0.2f
#define EPS_F 1e-16f

#define NB_SCAN ((N_NODES + 255) / 256)   // 391 scan blocks

// ---------------- scratch (device globals; no allocation allowed) ----------
__device__ float g_xl[(size_t)N_NODES * HC];
__device__ float g_xr[(size_t)N_NODES * HC];
__device__ int   g_deg[N_NODES];
__device__ int   g_tmp[N_NODES];        // per-chunk inclusive scan
__device__ int   g_rowstart[N_NODES];   // exclusive prefix
__device__ int   g_cursor[N_NODES];
__device__ int   g_part[NB_SCAN];       // block totals
__device__ int   g_part2[NB_SCAN];      // exclusive scan of totals
__device__ int   g_ssrc[N_EDGES];       // srcs bucketed by dst

__device__ __forceinline__ float lrelu(float v) {
    return fmaxf(v, 0.f) + NEG_SLOPE * fminf(v, 0.f);
}
__device__ __forceinline__ uint32_t to_tf32(float f) {
    uint32_t o;
    asm("cvt.rna.tf32.f32 %0, %1;" : "=r"(o) : "f"(f));
    return o;
}

// ---------------- K0: zero degree histogram ---------------------------------
__global__ void k_zero() {
    int i = blockIdx.x * 256 + threadIdx.x;
    if (i < N_NODES) g_deg[i] = 0;
}

// ---------------- K1: degree histogram --------------------------------------
__global__ __launch_bounds__(256) void k_degree(const int* __restrict__ ei) {
    int e = blockIdx.x * 256 + threadIdx.x;
    if (e < N_EDGES) atomicAdd(&g_deg[ei[N_EDGES + e]], 1);
}

// ---------------- K2a/b/c: two-level exclusive scan of degrees --------------
__global__ __launch_bounds__(256) void k_scan1() {
    __shared__ int s[256];
    int b = blockIdx.x, tid = threadIdx.x;
    int i = b * 256 + tid;
    int v = (i < N_NODES) ? g_deg[i] : 0;
    s[tid] = v;
    __syncthreads();
#pragma unroll
    for (int off = 1; off < 256; off <<= 1) {
        int t = (tid >= off) ? s[tid - off] : 0;
        __syncthreads();
        s[tid] += t;
        __syncthreads();
    }
    if (i < N_NODES) g_tmp[i] = s[tid];
    if (tid == 255) g_part[b] = s[255];
}
__global__ __launch_bounds__(512) void k_scan2() {
    __shared__ int s[512];
    int tid = threadIdx.x;
    int v = (tid < NB_SCAN) ? g_part[tid] : 0;
    s[tid] = v;
    __syncthreads();
#pragma unroll
    for (int off = 1; off < 512; off <<= 1) {
        int t = (tid >= off) ? s[tid - off] : 0;
        __syncthreads();
        s[tid] += t;
        __syncthreads();
    }
    if (tid < NB_SCAN) g_part2[tid] = s[tid] - v;   // exclusive
}
__global__ __launch_bounds__(256) void k_scan3() {
    int i = blockIdx.x * 256 + threadIdx.x;
    if (i >= N_NODES) return;
    int rs = g_tmp[i] - g_deg[i] + g_part2[i >> 8];
    g_rowstart[i] = rs;
    g_cursor[i]   = rs;
}

// ---------------- K3: bucket edges by destination ----------------------------
__global__ __launch_bounds__(256) void k_bucket(const int* __restrict__ ei) {
    int e = blockIdx.x * 256 + threadIdx.x;
    if (e >= N_EDGES) return;
    int src = ei[e];
    int dst = ei[N_EDGES + e];
    int pos = atomicAdd(&g_cursor[dst], 1);
    g_ssrc[pos] = src;
}

// ---------------- K4: fused dual GEMM via tf32 tensor-core mma --------------
__global__ __launch_bounds__(256) void k_gemm(
    const float* __restrict__ X,
    const float* __restrict__ Wl,
    const float* __restrict__ Wr)
{
    __shared__ uint32_t xs[64][36];
    __shared__ uint32_t ws[32][264];

    const int tid  = threadIdx.x;
    const int warp = tid >> 5;
    const int lane = tid & 31;
    const int r     = warp & 3;
    const int cHalf = warp >> 2;
    const int row0 = blockIdx.x * 64;
    const int qr = lane >> 2;
    const int ql = lane & 3;

    float c[16][4];
#pragma unroll
    for (int j = 0; j < 16; j++)
#pragma unroll
        for (int q = 0; q < 4; q++) c[j][q] = 0.f;

    for (int chunk = 0; chunk < 4; chunk++) {
        const int k0 = chunk * 32;
        if (chunk) __syncthreads();
#pragma unroll
        for (int i = 0; i < 2; i++) {
            int li = tid + i * 256;
            int m  = li >> 3;
            int kq = (li & 7) * 4;
            float4 v = make_float4(0.f, 0.f, 0.f, 0.f);
            if (row0 + m < N_NODES)
                v = *(const float4*)&X[(size_t)(row0 + m) * IN_CH + k0 + kq];
            xs[m][kq + 0] = to_tf32(v.x); xs[m][kq + 1] = to_tf32(v.y);
            xs[m][kq + 2] = to_tf32(v.z); xs[m][kq + 3] = to_tf32(v.w);
        }
#pragma unroll
        for (int i = 0; i < 8; i++) {
            int li = tid + i * 256;
            int k  = li >> 6;
            int cq = (li & 63) * 4;
            const float* Wsrc = (cq < 128) ? Wl : Wr;
            int cc = (cq < 128) ? cq : (cq - 128);
            float4 v = *(const float4*)&Wsrc[(size_t)(k0 + k) * HC + cc];
            ws[k][cq + 0] = to_tf32(v.x); ws[k][cq + 1] = to_tf32(v.y);
            ws[k][cq + 2] = to_tf32(v.z); ws[k][cq + 3] = to_tf32(v.w);
        }
        __syncthreads();

#pragma unroll
        for (int ks = 0; ks < 4; ks++) {
            const int kk = ks * 8;
            uint32_t a0 = xs[r * 16 + qr    ][kk + ql    ];
            uint32_t a1 = xs[r * 16 + qr + 8][kk + ql    ];
            uint32_t a2 = xs[r * 16 + qr    ][kk + ql + 4];
            uint32_t a3 = xs[r * 16 + qr + 8][kk + ql + 4];
#pragma unroll
            for (int j = 0; j < 16; j++) {
                int nb = cHalf * 128 + j * 8 + qr;
                uint32_t b0 = ws[kk + ql    ][nb];
                uint32_t b1 = ws[kk + ql + 4][nb];
                asm volatile(
                    "mma.sync.aligned.m16n8k8.row.col.f32.tf32.tf32.f32 "
                    "{%0,%1,%2,%3}, {%4,%5,%6,%7}, {%8,%9}, {%0,%1,%2,%3};"
                    : "+f"(c[j][0]), "+f"(c[j][1]), "+f"(c[j][2]), "+f"(c[j][3])
                    : "r"(a0), "r"(a1), "r"(a2), "r"(a3), "r"(b0), "r"(b1));
            }
        }
    }

    float* Y = cHalf ? g_xr : g_xl;
    const int rbase = row0 + r * 16 + qr;
#pragma unroll
    for (int j = 0; j < 16; j++) {
        int col = j * 8 + 2 * ql;
        if (rbase < N_NODES)
            *(float2*)&Y[(size_t)rbase * HC + col] = make_float2(c[j][0], c[j][1]);
        if (rbase + 8 < N_NODES)
            *(float2*)&Y[(size_t)(rbase + 8) * HC + col] = make_float2(c[j][2], c[j][3]);
    }
}

// ---------------- K5: per-node online-softmax aggregation -------------------
// one warp per node: lane group (lane>>3) = head, lane handles 4 channels.
// gathers x_l[src] ONCE per edge; no atomics; coalesced output.
__global__ __launch_bounds__(256) void k_aggregate(
    const float* __restrict__ att,
    const float* __restrict__ bias,
    float* __restrict__ out)
{
    int node = blockIdx.x * 8 + (threadIdx.x >> 5);
    if (node >= N_NODES) return;
    int lane = threadIdx.x & 31;

    float4 xr4 = *(const float4*)&g_xr[(size_t)node * HC + lane * 4];
    float4 t   = *(const float4*)&att[lane * 4];

    float m = -1e30f, d = 0.f;
    float4 acc = make_float4(0.f, 0.f, 0.f, 0.f);

    int start = g_rowstart[node];
    int n     = g_deg[node];

    for (int base = 0; base < n; base += 32) {
        int cnt = min(32, n - base);
        int myidx = start + base + lane;
        int mysrc = (lane < cnt) ? g_ssrc[myidx] : 0;
        for (int j = 0; j < cnt; j++) {
            int src = __shfl_sync(0xffffffffu, mysrc, j);
            float4 a = *(const float4*)&g_xl[(size_t)src * HC + lane * 4];

            float p = lrelu(a.x + xr4.x) * t.x;
            p = fmaf(lrelu(a.y + xr4.y), t.y, p);
            p = fmaf(lrelu(a.z + xr4.z), t.z, p);
            p = fmaf(lrelu(a.w + xr4.w), t.w, p);
            p += __shfl_xor_sync(0xffffffffu, p, 1);
            p += __shfl_xor_sync(0xffffffffu, p, 2);
            p += __shfl_xor_sync(0xffffffffu, p, 4);

            float nm = fmaxf(m, p);
            float s  = __expf(m - nm);     // 0 when m=-1e30
            float ee = __expf(p - nm);
            d = d * s + ee;
            acc.x = fmaf(acc.x, s, ee * a.x);
            acc.y = fmaf(acc.y, s, ee * a.y);
            acc.z = fmaf(acc.z, s, ee * a.z);
            acc.w = fmaf(acc.w, s, ee * a.w);
            m = nm;
        }
    }

    float inv = 1.f / (d + EPS_F);
    float4 b4 = *(const float4*)&bias[lane * 4];
    float4 o;
    o.x = fmaf(acc.x, inv, b4.x);
    o.y = fmaf(acc.y, inv, b4.y);
    o.z = fmaf(acc.z, inv, b4.z);
    o.w = fmaf(acc.w, inv, b4.w);
    *(float4*)&out[(size_t)node * HC + lane * 4] = o;
}

// ---------------- launch ----------------------------------------------------
extern "C" void kernel_launch(void* const* d_in, const int* in_sizes, int n_in,
                              void* d_out, int out_size)
{
    const float* x    = (const float*)d_in[0];
    const int*   ei   = (const int*)d_in[1];
    const float* Wl   = (const float*)d_in[2];
    const float* Wr   = (const float*)d_in[3];
    const float* att  = (const float*)d_in[4];
    const float* bias = (const float*)d_in[5];
    float* out = (float*)d_out;

    k_zero<<<NB_SCAN, 256>>>();
    k_degree<<<(N_EDGES + 255) / 256, 256>>>(ei);
    k_scan1<<<NB_SCAN, 256>>>();
    k_scan2<<<1, 512>>>();
    k_scan3<<<NB_SCAN, 256>>>();
    k_bucket<<<(N_EDGES + 255) / 256, 256>>>(ei);

    k_gemm<<<(N_NODES + 63) / 64, 256>>>(x, Wl, Wr);

    k_aggregate<<<(N_NODES + 7) / 8, 256>>>(att, bias, out);
}